// round 6
// baseline (speedup 1.0000x reference)
#include <cuda_runtime.h>
#include <math.h>

#define B_   32
#define C_   128
#define H_   56
#define W_   56
#define P_   (H_*W_)
#define E_   4
#define OUT_MAIN ((size_t)B_*C_*P_)

typedef unsigned long long ull;

// ---------------- scratch (device globals; no allocs allowed) ----------------
__device__ float g_pooled[B_*C_];
__device__ int   g_assign[B_];
__device__ float g_weights[B_*E_];
__device__ float g_cd_eff[C_*C_*9];
__device__ float g_bayar_eff[C_*C_*25];
__device__ float g_y[(size_t)B_*3*C_*P_];   // srm dw out (B,384,P); reused as hf dw out (B,128,P)
__device__ float g_z1[(size_t)B_*C_*P_];    // srm 1x1 out
__device__ float g_z2[(size_t)B_*C_*P_];    // hf 1x1 out
__device__ float g_mean1[C_], g_inv1[C_];
__device__ float g_mean2[C_], g_inv2[C_];

// ---------------- f32x2 packed helpers ----------------
__device__ __forceinline__ ull fma2(ull a, ull b, ull c) {
    ull d;
    asm("fma.rn.f32x2 %0, %1, %2, %3;" : "=l"(d) : "l"(a), "l"(b), "l"(c));
    return d;
}
__device__ __forceinline__ ull pkmid(ull a, ull b) {  // (hi(a), lo(b))
    ull r;
    asm("{\n\t.reg .f32 al, ah, bl, bh;\n\t"
        "mov.b64 {al, ah}, %1;\n\t"
        "mov.b64 {bl, bh}, %2;\n\t"
        "mov.b64 %0, {ah, bl};\n\t}"
        : "=l"(r) : "l"(a), "l"(b));
    return r;
}
__device__ __forceinline__ void upk(ull v, float& lo, float& hi) {
    asm("mov.b64 {%0, %1}, %2;" : "=f"(lo), "=f"(hi) : "l"(v));
}

// ---------------- pooling: mean over H,W per (b,c) ----------------
__global__ void pool_kernel(const float* __restrict__ x) {
    int bc = blockIdx.x;
    float s = 0.f;
    for (int p = threadIdx.x; p < P_; p += 256)
        s += x[(size_t)bc*P_ + p];
    __shared__ float sh[256];
    sh[threadIdx.x] = s;
    __syncthreads();
    for (int st = 128; st > 0; st >>= 1) {
        if (threadIdx.x < st) sh[threadIdx.x] += sh[threadIdx.x + st];
        __syncthreads();
    }
    if (threadIdx.x == 0) g_pooled[bc] = sh[0] / (float)P_;
}

// ---------------- gating + tail outputs ----------------
__global__ void gate_kernel(const float* __restrict__ Wg, float* __restrict__ out_tail,
                            int write_tail) {
    int tid = threadIdx.x;
    if (tid < B_) {
        float l[E_] = {0.f,0.f,0.f,0.f};
        for (int c = 0; c < C_; c++) {
            float p = g_pooled[tid*C_ + c];
            #pragma unroll
            for (int e = 0; e < E_; e++) l[e] += p * Wg[c*E_ + e];
        }
        int best = 0; float bv = l[0];
        #pragma unroll
        for (int e = 1; e < E_; e++) if (l[e] > bv) { bv = l[e]; best = e; }
        g_assign[tid] = best;
        #pragma unroll
        for (int e = 0; e < E_; e++) g_weights[tid*E_ + e] = (e == best) ? 1.f : 0.f;
    }
    __syncthreads();
    if (tid == 0 && write_tail) {
        float cnt[E_] = {0.f,0.f,0.f,0.f};
        for (int b = 0; b < B_; b++) cnt[g_assign[b]] += 1.f;
        float mean = (float)B_ / (float)E_;
        float var = 0.f;
        for (int e = 0; e < E_; e++) { float d = cnt[e]-mean; var += d*d; }
        var /= (float)E_;
        out_tail[0] = var / (mean*mean + 1e-10f);
        for (int e = 0; e < E_; e++) out_tail[1+e] = cnt[e];
        for (int e = 0; e < E_; e++) out_tail[5+e] = cnt[e];
        for (int i = 0; i < B_*E_; i++) out_tail[9+i] = g_weights[i];
    }
}

// ---------------- weight prep ----------------
__global__ void prep_cd_kernel(const float* __restrict__ cd_w) {
    int oi = blockIdx.x*256 + threadIdx.x;
    if (oi >= C_*C_) return;
    float v[9]; float s = 0.f;
    #pragma unroll
    for (int k = 0; k < 9; k++) { v[k] = cd_w[oi*9 + k]; s += v[k]; }
    v[4] -= 0.7f * s;
    #pragma unroll
    for (int k = 0; k < 9; k++) g_cd_eff[oi*9 + k] = v[k];
}

__global__ void prep_bayar_kernel(const float* __restrict__ raw) {
    int oi = blockIdx.x*256 + threadIdx.x;
    if (oi >= C_*C_) return;
    float v[24]; float s = 0.f;
    #pragma unroll
    for (int k = 0; k < 24; k++) { v[k] = raw[oi*24 + k]; s += v[k]; }
    float invs = 1.f / s;
    #pragma unroll
    for (int k = 0; k < 12; k++) g_bayar_eff[oi*25 + k] = v[k]*invs;
    g_bayar_eff[oi*25 + 12] = -1.f;
    #pragma unroll
    for (int k = 12; k < 24; k++) g_bayar_eff[oi*25 + k + 1] = v[k]*invs;
}

// ---------------- 3x3 dense conv, f32x2 packed ----------------
// Block: 128 thr; tile 16x16 px x 32 co; thread: 4x4 px (2 pixel-pairs x 4 rows) x 4 co.
template<bool ACCUM, int WSRC>
__global__ __launch_bounds__(128, 3)
void conv3_kernel(const float* __restrict__ x, const float* __restrict__ wext,
                  float* __restrict__ out, int sel) {
    const int b = blockIdx.z >> 2;
    if (sel >= 0 && g_assign[b] != sel) return;
    const int co0 = (blockIdx.z & 3) * 32;
    const int h0 = blockIdx.y * 16, w0 = blockIdx.x * 16;
    const float* wptr = (WSRC == 1) ? g_cd_eff : wext;
    __shared__ float xs[8][18][20];
    __shared__ float2 ws[8][9][8][5];   // [ci][tap][cog][co-slot(4)+pad]
    const int tid = threadIdx.x;
    const int cog = tid & 7;
    const int quad = tid >> 3;
    const int qy = (quad >> 2) * 4, qx = (quad & 3) * 4;

    ull acc[4][4][2];
    #pragma unroll
    for (int j = 0; j < 4; j++)
        #pragma unroll
        for (int r = 0; r < 4; r++) { acc[j][r][0] = 0ull; acc[j][r][1] = 0ull; }

    for (int cc = 0; cc < C_; cc += 8) {
        for (int idx = tid; idx < 8*18*18; idx += 128) {
            int ci = idx / 324, r = idx % 324;
            int ry = r / 18, rx = r % 18;
            int hh = h0 - 1 + ry, wwi = w0 - 1 + rx;
            float v = 0.f;
            if (hh >= 0 && hh < H_ && wwi >= 0 && wwi < W_)
                v = x[((size_t)(b*C_ + cc + ci)*H_ + hh)*W_ + wwi];
            xs[ci][ry][rx] = v;
        }
        for (int idx = tid; idx < 32*8*9; idx += 128) {
            int co = idx / 72, rem = idx % 72;
            int ci = rem / 9, k = rem % 9;
            float wv = wptr[((size_t)(co0 + co)*C_ + cc + ci)*9 + k];
            ws[ci][k][co >> 2][co & 3] = make_float2(wv, wv);
        }
        __syncthreads();
        #pragma unroll
        for (int ci = 0; ci < 8; ci++) {
            #pragma unroll
            for (int ky = 0; ky < 3; ky++) {
                ull wv[4][3];
                #pragma unroll
                for (int j = 0; j < 4; j++)
                    #pragma unroll
                    for (int kx = 0; kx < 3; kx++)
                        wv[j][kx] = *(const ull*)&ws[ci][ky*3 + kx][cog][j];
                #pragma unroll
                for (int r = 0; r < 4; r++) {
                    const float* row = &xs[ci][qy + r + ky][qx];
                    ulonglong2 L = *(const ulonglong2*)row;      // P0, P2
                    ull P4 = *(const ull*)(row + 4);
                    ull P0 = L.x, P2 = L.y;
                    ull P1 = pkmid(P0, P2);
                    ull P3 = pkmid(P2, P4);
                    #pragma unroll
                    for (int j = 0; j < 4; j++) {
                        acc[j][r][0] = fma2(wv[j][0], P0, acc[j][r][0]);
                        acc[j][r][0] = fma2(wv[j][1], P1, acc[j][r][0]);
                        acc[j][r][0] = fma2(wv[j][2], P2, acc[j][r][0]);
                        acc[j][r][1] = fma2(wv[j][0], P2, acc[j][r][1]);
                        acc[j][r][1] = fma2(wv[j][1], P3, acc[j][r][1]);
                        acc[j][r][1] = fma2(wv[j][2], P4, acc[j][r][1]);
                    }
                }
            }
        }
        __syncthreads();
    }
    #pragma unroll
    for (int j = 0; j < 4; j++) {
        int co = co0 + cog*4 + j;
        #pragma unroll
        for (int r = 0; r < 4; r++) {
            int hh = h0 + qy + r;
            if (hh >= H_) continue;
            #pragma unroll
            for (int pr = 0; pr < 2; pr++) {
                int wwi = w0 + qx + pr*2;
                float lo, hi;
                upk(acc[j][r][pr], lo, hi);
                size_t o = ((size_t)(b*C_ + co)*H_ + hh)*W_ + wwi;
                if (wwi < W_)     { if (ACCUM) out[o]   += lo; else out[o]   = lo; }
                if (wwi + 1 < W_) { if (ACCUM) out[o+1] += hi; else out[o+1] = hi; }
            }
        }
    }
}

// ---------------- 5x5 dense conv (bayar), f32x2 packed ----------------
// Block: 256 thr; tile 16x16 px x 32 co; thread: 4x4 px x 2 co.
template<bool ACCUM>
__global__ __launch_bounds__(256, 2)
void conv5_kernel(const float* __restrict__ x, float* __restrict__ out, int sel) {
    const int b = blockIdx.z >> 2;
    if (g_assign[b] != sel) return;
    const int co0 = (blockIdx.z & 3) * 32;
    const int h0 = blockIdx.y * 16, w0 = blockIdx.x * 16;
    __shared__ float xs[4][20][24];
    __shared__ float2 ws[4][25][16][3];  // [ci][tap][cog][co-slot(2)+pad]
    const int tid = threadIdx.x;
    const int cog = tid & 15;
    const int quad = tid >> 4;
    const int qy = (quad >> 2) * 4, qx = (quad & 3) * 4;

    ull acc[2][4][2];
    #pragma unroll
    for (int j = 0; j < 2; j++)
        #pragma unroll
        for (int r = 0; r < 4; r++) { acc[j][r][0] = 0ull; acc[j][r][1] = 0ull; }

    for (int cc = 0; cc < C_; cc += 4) {
        for (int idx = tid; idx < 4*20*20; idx += 256) {
            int ci = idx / 400, r = idx % 400;
            int ry = r / 20, rx = r % 20;
            int hh = h0 - 2 + ry, wwi = w0 - 2 + rx;
            float v = 0.f;
            if (hh >= 0 && hh < H_ && wwi >= 0 && wwi < W_)
                v = x[((size_t)(b*C_ + cc + ci)*H_ + hh)*W_ + wwi];
            xs[ci][ry][rx] = v;
        }
        for (int idx = tid; idx < 32*4*25; idx += 256) {
            int co = idx / 100, rem = idx % 100;
            int ci = rem / 25, k = rem % 25;
            float wv = g_bayar_eff[((size_t)(co0 + co)*C_ + cc + ci)*25 + k];
            ws[ci][k][co >> 1][co & 1] = make_float2(wv, wv);
        }
        __syncthreads();
        #pragma unroll
        for (int ci = 0; ci < 4; ci++) {
            #pragma unroll
            for (int ky = 0; ky < 5; ky++) {
                ull wv[2][5];
                #pragma unroll
                for (int j = 0; j < 2; j++)
                    #pragma unroll
                    for (int kx = 0; kx < 5; kx++)
                        wv[j][kx] = *(const ull*)&ws[ci][ky*5 + kx][cog][j];
                #pragma unroll
                for (int r = 0; r < 4; r++) {
                    const float* row = &xs[ci][qy + r + ky][qx];
                    ulonglong2 L0 = *(const ulonglong2*)row;        // P0, P2
                    ulonglong2 L1 = *(const ulonglong2*)(row + 4);  // P4, P6
                    ull Ppk[7];
                    Ppk[0] = L0.x; Ppk[2] = L0.y; Ppk[4] = L1.x; Ppk[6] = L1.y;
                    Ppk[1] = pkmid(Ppk[0], Ppk[2]);
                    Ppk[3] = pkmid(Ppk[2], Ppk[4]);
                    Ppk[5] = pkmid(Ppk[4], Ppk[6]);
                    #pragma unroll
                    for (int j = 0; j < 2; j++) {
                        #pragma unroll
                        for (int kx = 0; kx < 5; kx++) {
                            acc[j][r][0] = fma2(wv[j][kx], Ppk[kx],     acc[j][r][0]);
                            acc[j][r][1] = fma2(wv[j][kx], Ppk[kx + 2], acc[j][r][1]);
                        }
                    }
                }
            }
        }
        __syncthreads();
    }
    #pragma unroll
    for (int j = 0; j < 2; j++) {
        int co = co0 + cog*2 + j;
        #pragma unroll
        for (int r = 0; r < 4; r++) {
            int hh = h0 + qy + r;
            if (hh >= H_) continue;
            #pragma unroll
            for (int pr = 0; pr < 2; pr++) {
                int wwi = w0 + qx + pr*2;
                float lo, hi;
                upk(acc[j][r][pr], lo, hi);
                size_t o = ((size_t)(b*C_ + co)*H_ + hh)*W_ + wwi;
                if (wwi < W_)     { if (ACCUM) out[o]   += lo; else out[o]   = lo; }
                if (wwi + 1 < W_) { if (ACCUM) out[o+1] += hi; else out[o+1] = hi; }
            }
        }
    }
}

// ---------------- srm depthwise 5x5 + hardtanh ----------------
__global__ void dw_srm_kernel(const float* __restrict__ x, const float* __restrict__ kern) {
    int b = blockIdx.x / C_, c = blockIdx.x % C_;
    __shared__ float xs[60][60];
    __shared__ float kf[3][25];
    int tid = threadIdx.x;  // 256
    for (int idx = tid; idx < 60*60; idx += 256) {
        int ry = idx / 60, rx = idx % 60;
        int hh = ry - 2, wi = rx - 2;
        float v = 0.f;
        if (hh >= 0 && hh < H_ && wi >= 0 && wi < W_)
            v = x[((size_t)(b*C_ + c)*H_ + hh)*W_ + wi];
        xs[ry][rx] = v;
    }
    if (tid < 75) kf[tid/25][tid%25] = kern[(c*3 + tid/25)*25 + tid%25];
    __syncthreads();
    for (int p = tid; p < P_; p += 256) {
        int hh = p / W_, wi = p % W_;
        float a0 = 0.f, a1 = 0.f, a2 = 0.f;
        #pragma unroll
        for (int ky = 0; ky < 5; ky++)
            #pragma unroll
            for (int kx = 0; kx < 5; kx++) {
                float v = xs[hh+ky][wi+kx];
                a0 += kf[0][ky*5+kx]*v;
                a1 += kf[1][ky*5+kx]*v;
                a2 += kf[2][ky*5+kx]*v;
            }
        a0 = fminf(fmaxf(a0, -3.f), 3.f);
        a1 = fminf(fmaxf(a1, -3.f), 3.f);
        a2 = fminf(fmaxf(a2, -3.f), 3.f);
        size_t base = ((size_t)b*3*C_ + c*3)*P_ + p;
        g_y[base        ] = a0;
        g_y[base +   P_ ] = a1;
        g_y[base + 2*P_ ] = a2;
    }
}

// ---------------- hf depthwise 3x3 ----------------
__global__ void dw_hf_kernel(const float* __restrict__ x, const float* __restrict__ kern) {
    int b = blockIdx.x / C_, c = blockIdx.x % C_;
    __shared__ float xs[58][58];
    __shared__ float kf[9];
    int tid = threadIdx.x;  // 256
    for (int idx = tid; idx < 58*58; idx += 256) {
        int ry = idx / 58, rx = idx % 58;
        int hh = ry - 1, wi = rx - 1;
        float v = 0.f;
        if (hh >= 0 && hh < H_ && wi >= 0 && wi < W_)
            v = x[((size_t)(b*C_ + c)*H_ + hh)*W_ + wi];
        xs[ry][rx] = v;
    }
    if (tid < 9) kf[tid] = kern[c*9 + tid];
    __syncthreads();
    for (int p = tid; p < P_; p += 256) {
        int hh = p / W_, wi = p % W_;
        float a = 0.f;
        #pragma unroll
        for (int ky = 0; ky < 3; ky++)
            #pragma unroll
            for (int kx = 0; kx < 3; kx++)
                a += kf[ky*3+kx] * xs[hh+ky][wi+kx];
        g_y[((size_t)(b*C_ + c))*P_ + p] = a;
    }
}

// ---------------- 1x1 conv GEMM, f32x2 packed ----------------
// Tile: 128 co x 64 px; 256 thr; thread: 8 co x 4 px (2 pairs).
template<int KD, int ZSEL>
__global__ __launch_bounds__(256)
void gemm2_kernel(const float* __restrict__ wmat) {
    float* z = (ZSEL == 0) ? g_z1 : g_z2;
    const int b = blockIdx.z;
    const int p0 = blockIdx.x * 64;
    __shared__ float yssh[16][64];
    __shared__ float2 wssh[16][128];
    const int tid = threadIdx.x;
    const int tc = tid >> 4, tp = tid & 15;
    ull acc[8][2];
    #pragma unroll
    for (int j = 0; j < 8; j++) { acc[j][0] = 0ull; acc[j][1] = 0ull; }

    for (int kk = 0; kk < KD; kk += 16) {
        for (int idx = tid; idx < 1024; idx += 256) {
            int k = idx >> 6, p = idx & 63;
            yssh[k][p] = g_y[(size_t)b*KD*P_ + (size_t)(kk + k)*P_ + p0 + p];
        }
        for (int idx = tid; idx < 2048; idx += 256) {
            int k = idx >> 7, co = idx & 127;
            float wv = wmat[(size_t)co*KD + kk + k];
            wssh[k][co] = make_float2(wv, wv);
        }
        __syncthreads();
        #pragma unroll
        for (int k = 0; k < 16; k++) {
            ulonglong2 Y = *(const ulonglong2*)&yssh[k][tp*4];
            #pragma unroll
            for (int j = 0; j < 8; j++) {
                ull w = *(const ull*)&wssh[k][tc*8 + j];
                acc[j][0] = fma2(w, Y.x, acc[j][0]);
                acc[j][1] = fma2(w, Y.y, acc[j][1]);
            }
        }
        __syncthreads();
    }
    #pragma unroll
    for (int j = 0; j < 8; j++) {
        int co = tc*8 + j;
        size_t base = ((size_t)(b*C_ + co))*P_ + p0 + tp*4;
        float lo, hi;
        upk(acc[j][0], lo, hi);
        *(float2*)&z[base] = make_float2(lo, hi);
        upk(acc[j][1], lo, hi);
        *(float2*)&z[base + 2] = make_float2(lo, hi);
    }
}

// ---------------- BN statistics over (B,H,W) per channel ----------------
__global__ void bn_stats2_kernel(int zsel) {
    const float* z = (zsel == 0) ? g_z1 : g_z2;
    int c = blockIdx.x;
    double s = 0.0, s2 = 0.0;
    for (int t = threadIdx.x; t < B_*(P_/4); t += 256) {
        int b = t / (P_/4), q = t % (P_/4);
        float4 v = ((const float4*)&z[((size_t)(b*C_ + c))*P_])[q];
        s  += (double)v.x + (double)v.y + (double)v.z + (double)v.w;
        s2 += (double)v.x*v.x + (double)v.y*v.y + (double)v.z*v.z + (double)v.w*v.w;
    }
    __shared__ double sh[256], sh2[256];
    sh[threadIdx.x] = s; sh2[threadIdx.x] = s2;
    __syncthreads();
    for (int st = 128; st > 0; st >>= 1) {
        if (threadIdx.x < st) { sh[threadIdx.x] += sh[threadIdx.x+st]; sh2[threadIdx.x] += sh2[threadIdx.x+st]; }
        __syncthreads();
    }
    if (threadIdx.x == 0) {
        double n = (double)B_*P_;
        double m = sh[0] / n;
        double var = sh2[0] / n - m*m;
        if (zsel == 0) { g_mean1[c] = (float)m; g_inv1[c] = (float)(1.0 / sqrt(var + 1e-5)); }
        else           { g_mean2[c] = (float)m; g_inv2[c] = (float)(1.0 / sqrt(var + 1e-5)); }
    }
}

// ---------------- BN apply + ReLU + gated accumulate ----------------
__global__ void bn_apply2_kernel(float* __restrict__ out, const float* __restrict__ gamma,
                                 const float* __restrict__ beta, int zsel, int sel) {
    int b = blockIdx.x / C_, c = blockIdx.x % C_;
    if (g_assign[b] != sel) return;
    const float* z = (zsel == 0) ? g_z1 : g_z2;
    float m   = (zsel == 0) ? g_mean1[c] : g_mean2[c];
    float inv = (zsel == 0) ? g_inv1[c]  : g_inv2[c];
    float sc = inv * gamma[c];
    float shft = beta[c] - m * sc;
    const float4* zp = (const float4*)&z[((size_t)(b*C_ + c))*P_];
    float4* op = (float4*)&out[((size_t)(b*C_ + c))*P_];
    for (int q = threadIdx.x; q < P_/4; q += 256) {
        float4 v = zp[q];
        float4 o = op[q];
        o.x += fmaxf(v.x*sc + shft, 0.f);
        o.y += fmaxf(v.y*sc + shft, 0.f);
        o.z += fmaxf(v.z*sc + shft, 0.f);
        o.w += fmaxf(v.w*sc + shft, 0.f);
        op[q] = o;
    }
}

// ---------------- launch (single stream, fully capture-safe) ----------------
extern "C" void kernel_launch(void* const* d_in, const int* in_sizes, int n_in,
                              void* d_out, int out_size) {
    const float* x          = (const float*)d_in[0];
    const float* Wg         = (const float*)d_in[1];
    const float* cd_w       = (const float*)d_in[2];
    const float* bayar_w    = (const float*)d_in[3];
    const float* srm_kernel = (const float*)d_in[4];
    const float* srm_out_w  = (const float*)d_in[5];
    const float* srm_gamma  = (const float*)d_in[6];
    const float* srm_beta   = (const float*)d_in[7];
    const float* hf_kernel  = (const float*)d_in[8];
    const float* hf_out_w   = (const float*)d_in[9];
    const float* hf_gamma   = (const float*)d_in[10];
    const float* hf_beta    = (const float*)d_in[11];
    const float* shared_w   = (const float*)d_in[12];
    float* out = (float*)d_out;

    int write_tail = ((size_t)out_size >= OUT_MAIN + 137) ? 1 : 0;

    pool_kernel<<<B_*C_, 256>>>(x);
    gate_kernel<<<1, 128>>>(Wg, out + OUT_MAIN, write_tail);
    prep_cd_kernel<<<(C_*C_ + 255)/256, 256>>>(cd_w);
    prep_bayar_kernel<<<(C_*C_ + 255)/256, 256>>>(bayar_w);

    // conv family
    conv3_kernel<false,0><<<dim3(4,4,B_*4), 128>>>(x, shared_w, out, -1);   // shared, all b
    conv3_kernel<true,1><<<dim3(4,4,B_*4), 128>>>(x, nullptr, out, 0);      // cd, gated
    conv5_kernel<true><<<dim3(4,4,B_*4), 256>>>(x, out, 1);                 // bayar, gated

    // srm expert: full batch (BN stats), gated add
    dw_srm_kernel<<<B_*C_, 256>>>(x, srm_kernel);
    gemm2_kernel<3*C_, 0><<<dim3(49,1,B_), 256>>>(srm_out_w);
    bn_stats2_kernel<<<C_, 256>>>(0);
    bn_apply2_kernel<<<B_*C_, 256>>>(out, srm_gamma, srm_beta, 0, 2);

    // hf expert: full batch, gated add
    dw_hf_kernel<<<B_*C_, 256>>>(x, hf_kernel);
    gemm2_kernel<C_, 1><<<dim3(49,1,B_), 256>>>(hf_out_w);
    bn_stats2_kernel<<<C_, 256>>>(1);
    bn_apply2_kernel<<<B_*C_, 256>>>(out, hf_gamma, hf_beta, 1, 3);
}